// round 7
// baseline (speedup 1.0000x reference)
#include <cuda_runtime.h>
#include <cuda_fp16.h>
#include <math_constants.h>

// TropConv2D: x (8,32,32,32) f32, w (288,64) f32, bias (64) f32
// out (8,30,30,64) f32: max_k(p_k + w_kf) - min_k(p_k + w_kf) + bias_f
// K = 3*3*32, k = (ii*3 + jj)*32 + c (channel fastest)
//
// R6: filter-split warps for occupancy. Warp = 2 pixels x 32 filters
// (lane = one filter, channel pairs packed in half2). 7200 warps (76% occ),
// no smem (w read via L1-resident LDG.128), near-zero addressing in the
// fully-unrolled loop.

#define HO_ 30
#define WO_ 30

__device__ uint4 g_x8[32768];   // x as half, 8 consecutive channels per entry
__device__ uint4 g_w4[2304];    // [ij*256 + q*64 + f]: channel-pairs 4q..4q+3, filter f

__device__ __forceinline__ unsigned packh2(float a, float b) {
    __half2 h = __floats2half2_rn(a, b);
    return *reinterpret_cast<unsigned*>(&h);
}
__device__ __forceinline__ __half2 as_h2(unsigned u) {
    return *reinterpret_cast<__half2*>(&u);
}

__global__ __launch_bounds__(256)
void trop_prepass(const float4* __restrict__ x4, const float* __restrict__ w)
{
    const int t = blockIdx.x * 256 + threadIdx.x;   // grid covers 35072 = 137*256
    if (t < 32768) {
        const float4 a = x4[2 * t];
        const float4 b = x4[2 * t + 1];
        uint4 u;
        u.x = packh2(a.x, a.y);
        u.y = packh2(a.z, a.w);
        u.z = packh2(b.x, b.y);
        u.w = packh2(b.z, b.w);
        g_x8[t] = u;
    } else if (t < 35072) {
        const int wi = t - 32768;        // 0..2303
        const int f  = wi & 63;
        const int q  = (wi >> 6) & 3;
        const int ij = wi >> 8;
        const int k0 = ij * 32 + q * 8;
        uint4 u;
        u.x = packh2(w[(k0 + 0) * 64 + f], w[(k0 + 1) * 64 + f]);
        u.y = packh2(w[(k0 + 2) * 64 + f], w[(k0 + 3) * 64 + f]);
        u.z = packh2(w[(k0 + 4) * 64 + f], w[(k0 + 5) * 64 + f]);
        u.w = packh2(w[(k0 + 6) * 64 + f], w[(k0 + 7) * 64 + f]);
        g_w4[wi] = u;
    }
}

__global__ __launch_bounds__(128)
void trop_main(const float* __restrict__ bias, float* __restrict__ out)
{
    const int wg   = blockIdx.x * 4 + (threadIdx.x >> 5);  // 0..7199
    const int lane = threadIdx.x & 31;
    const int pp   = wg >> 1;            // pixel pair 0..3599
    const int f    = (wg & 1) * 32 + lane;
    const int pix0 = pp * 2;

    int xb[2];
    #pragma unroll
    for (int px = 0; px < 2; px++) {
        const int pix = pix0 + px;
        const int b  = pix / (HO_ * WO_);
        const int r  = pix - b * (HO_ * WO_);
        const int ho = r / WO_;
        const int wo = r - ho * WO_;
        xb[px] = ((b * 32 + ho) * 32 + wo) * 4;   // uint4 index (8 halves each)
    }

    const uint4* __restrict__ wb = g_w4 + f;      // + (ij*4+q)*64, const offsets

    const __half2 PINF = __float2half2_rn(CUDART_INF_F);
    const __half2 NINF = __float2half2_rn(-CUDART_INF_F);
    __half2 mxA[2], mxB[2], mnA[2], mnB[2];
    #pragma unroll
    for (int px = 0; px < 2; px++) {
        mxA[px] = NINF; mxB[px] = NINF;
        mnA[px] = PINF; mnB[px] = PINF;
    }

    #pragma unroll
    for (int ij = 0; ij < 9; ij++) {
        const int ii  = ij / 3;
        const int jj  = ij - ii * 3;
        const int tap = (ii * 32 + jj) * 4;       // uint4 offset of this window tap

        #pragma unroll
        for (int q = 0; q < 4; q++) {
            const uint4 wv = __ldg(wb + (ij * 4 + q) * 64);
            const __half2 w0 = as_h2(wv.x), w1 = as_h2(wv.y),
                          w2 = as_h2(wv.z), w3 = as_h2(wv.w);

            #pragma unroll
            for (int px = 0; px < 2; px++) {
                const uint4 xv = __ldg(&g_x8[xb[px] + tap + q]);  // broadcast
                const __half2 p0 = as_h2(xv.x), p1 = as_h2(xv.y),
                              p2 = as_h2(xv.z), p3 = as_h2(xv.w);
                __half2 s;
                s = __hadd2(p0, w0); mxA[px] = __hmax2(mxA[px], s); mnA[px] = __hmin2(mnA[px], s);
                s = __hadd2(p1, w1); mxB[px] = __hmax2(mxB[px], s); mnB[px] = __hmin2(mnB[px], s);
                s = __hadd2(p2, w2); mxA[px] = __hmax2(mxA[px], s); mnA[px] = __hmin2(mnA[px], s);
                s = __hadd2(p3, w3); mxB[px] = __hmax2(mxB[px], s); mnB[px] = __hmin2(mnB[px], s);
            }
        }
    }

    const float bf = bias[f];
    #pragma unroll
    for (int px = 0; px < 2; px++) {
        const __half2 mx = __hmax2(mxA[px], mxB[px]);
        const __half2 mn = __hmin2(mnA[px], mnB[px]);
        const float m = fmaxf(__low2float(mx), __high2float(mx));
        const float n = fminf(__low2float(mn), __high2float(mn));
        out[(pix0 + px) * 64 + f] = m - n + bf;
    }
}

extern "C" void kernel_launch(void* const* d_in, const int* in_sizes, int n_in,
                              void* d_out, int out_size)
{
    const float* x    = (const float*)d_in[0];   // 262144
    const float* w    = (const float*)d_in[1];   // 18432
    const float* bias = (const float*)d_in[2];   // 64
    float* out = (float*)d_out;                  // 460800

    trop_prepass<<<137, 256>>>((const float4*)x, w);
    // 7200 warps: 2 pixels x 32 filters each; 1800 blocks of 128 threads
    trop_main<<<1800, 128>>>(bias, out);
}

// round 8
// speedup vs baseline: 1.1605x; 1.1605x over previous
#include <cuda_runtime.h>
#include <cuda_fp16.h>
#include <math_constants.h>

// TropConv2D: x (8,32,32,32) f32, w (288,64) f32, bias (64) f32
// out (8,30,30,64) f32: max_k(p_k + w_kf) - min_k(p_k + w_kf) + bias_f
// K = 3*3*32, k = (ii*3 + jj)*32 + c (channel fastest)
//
// R7: warp = 4 pixels x 32 filters (lane = filter), 3600 warps.
// fp16x2 semiring (HADD2/HMNMX2). Explicit 2-stage software pipeline:
// prefetch step s+1 loads (1 w-uint4 + 4 broadcast x-uint4) while computing
// step s (48 compute insts) -> load latency fully hidden.

#define HO_ 30
#define WO_ 30

__device__ uint4 g_x8[32768];   // x as half, 8 consecutive channels per entry
__device__ uint4 g_w4[2304];    // [(ij*4+q)*64 + f]: channel-pairs 4q..4q+3, filter f

__device__ __forceinline__ unsigned packh2(float a, float b) {
    __half2 h = __floats2half2_rn(a, b);
    return *reinterpret_cast<unsigned*>(&h);
}
__device__ __forceinline__ __half2 as_h2(unsigned u) {
    return *reinterpret_cast<__half2*>(&u);
}

__global__ __launch_bounds__(256)
void trop_prepass(const float4* __restrict__ x4, const float* __restrict__ w)
{
    const int t = blockIdx.x * 256 + threadIdx.x;   // grid covers 35072 = 137*256
    if (t < 32768) {
        const float4 a = x4[2 * t];
        const float4 b = x4[2 * t + 1];
        uint4 u;
        u.x = packh2(a.x, a.y);
        u.y = packh2(a.z, a.w);
        u.z = packh2(b.x, b.y);
        u.w = packh2(b.z, b.w);
        g_x8[t] = u;
    } else if (t < 35072) {
        const int wi = t - 32768;        // 0..2303
        const int f  = wi & 63;
        const int q  = (wi >> 6) & 3;
        const int ij = wi >> 8;
        const int k0 = ij * 32 + q * 8;
        uint4 u;
        u.x = packh2(w[(k0 + 0) * 64 + f], w[(k0 + 1) * 64 + f]);
        u.y = packh2(w[(k0 + 2) * 64 + f], w[(k0 + 3) * 64 + f]);
        u.z = packh2(w[(k0 + 4) * 64 + f], w[(k0 + 5) * 64 + f]);
        u.w = packh2(w[(k0 + 6) * 64 + f], w[(k0 + 7) * 64 + f]);
        g_w4[wi] = u;
    }
}

// uint4 offset of pipeline step s (s = ij*4 + q) within a pixel's x block
__device__ __forceinline__ int x_step_ofs(int s) {
    const int ij = s >> 2;
    const int q  = s & 3;
    const int ii = ij / 3;
    const int jj = ij - ii * 3;
    return (ii * 32 + jj) * 4 + q;
}

__global__ __launch_bounds__(256, 3)
void trop_main(const float* __restrict__ bias, float* __restrict__ out)
{
    const int wg   = blockIdx.x * 8 + (threadIdx.x >> 5);  // 0..3599
    const int lane = threadIdx.x & 31;
    const int pg   = wg >> 1;                // pixel group 0..1799 (4 px each)
    const int f    = (wg & 1) * 32 + lane;   // this warp's filter half
    const int pix0 = pg * 4;

    int xb[4];
    #pragma unroll
    for (int px = 0; px < 4; px++) {
        const int pix = pix0 + px;
        const int b  = pix / (HO_ * WO_);
        const int r  = pix - b * (HO_ * WO_);
        const int ho = r / WO_;
        const int wo = r - ho * WO_;
        xb[px] = ((b * 32 + ho) * 32 + wo) * 4;   // uint4 index (8 halves each)
    }

    const uint4* __restrict__ wb = g_w4 + f;

    const __half2 PINF = __float2half2_rn(CUDART_INF_F);
    const __half2 NINF = __float2half2_rn(-CUDART_INF_F);
    __half2 mxa[4], mxb[4], mna[4], mnb[4];   // 2 acc pairs per px (even/odd h2)
    #pragma unroll
    for (int px = 0; px < 4; px++) {
        mxa[px] = NINF; mxb[px] = NINF;
        mna[px] = PINF; mnb[px] = PINF;
    }

    // ── software pipeline: preload step 0 ──
    uint4 wc = __ldg(wb);
    uint4 xc[4];
    #pragma unroll
    for (int px = 0; px < 4; px++) xc[px] = __ldg(&g_x8[xb[px]]);

    #pragma unroll
    for (int s = 0; s < 36; s++) {
        // prefetch step s+1 while computing step s
        uint4 wn;
        uint4 xn[4];
        if (s + 1 < 36) {
            wn = __ldg(wb + (s + 1) * 64);
            const int o = x_step_ofs(s + 1);
            #pragma unroll
            for (int px = 0; px < 4; px++) xn[px] = __ldg(&g_x8[xb[px] + o]);
        }

        const __half2 w0 = as_h2(wc.x), w1 = as_h2(wc.y),
                      w2 = as_h2(wc.z), w3 = as_h2(wc.w);
        #pragma unroll
        for (int px = 0; px < 4; px++) {
            const __half2 p0 = as_h2(xc[px].x), p1 = as_h2(xc[px].y),
                          p2 = as_h2(xc[px].z), p3 = as_h2(xc[px].w);
            __half2 s0 = __hadd2(p0, w0);
            __half2 s1 = __hadd2(p1, w1);
            __half2 s2 = __hadd2(p2, w2);
            __half2 s3 = __hadd2(p3, w3);
            mxa[px] = __hmax2(mxa[px], s0); mna[px] = __hmin2(mna[px], s0);
            mxb[px] = __hmax2(mxb[px], s1); mnb[px] = __hmin2(mnb[px], s1);
            mxa[px] = __hmax2(mxa[px], s2); mna[px] = __hmin2(mna[px], s2);
            mxb[px] = __hmax2(mxb[px], s3); mnb[px] = __hmin2(mnb[px], s3);
        }

        if (s + 1 < 36) {
            wc = wn;
            #pragma unroll
            for (int px = 0; px < 4; px++) xc[px] = xn[px];
        }
    }

    const float bf = bias[f];
    #pragma unroll
    for (int px = 0; px < 4; px++) {
        const __half2 mx = __hmax2(mxa[px], mxb[px]);
        const __half2 mn = __hmin2(mna[px], mnb[px]);
        const float m = fmaxf(__low2float(mx), __high2float(mx));
        const float n = fminf(__low2float(mn), __high2float(mn));
        out[(pix0 + px) * 64 + f] = m - n + bf;
    }
}

extern "C" void kernel_launch(void* const* d_in, const int* in_sizes, int n_in,
                              void* d_out, int out_size)
{
    const float* x    = (const float*)d_in[0];   // 262144
    const float* w    = (const float*)d_in[1];   // 18432
    const float* bias = (const float*)d_in[2];   // 64
    float* out = (float*)d_out;                  // 460800

    trop_prepass<<<137, 256>>>((const float4*)x, w);
    // 3600 warps: 4 pixels x 32 filters each; 450 blocks of 256 threads
    trop_main<<<450, 256>>>(bias, out);
}